// round 3
// baseline (speedup 1.0000x reference)
#include <cuda_runtime.h>

typedef unsigned int u32;
typedef unsigned long long u64;

#define NVOX 262144
#define PMX (-74.88f)
#define PMY (-74.88f)
#define PMZ (-2.0f)
#define VS  (0.32f)
#define BN_EPS 1e-3f

// ---------------- device scratch (no allocation allowed) --------------------
static __device__ float pv_cnt[NVOX];
static __device__ float pv_vmean[NVOX * 3];
static __device__ u32   pv_seg1[NVOX * 32];   // ordered-uint raw max, layer 1
static __device__ u32   pv_seg2[NVOX * 64];   // ordered-uint raw max, layer 2
static __device__ float pv_xmax[NVOX * 32];   // finalized layer-1 voxel feats
static __device__ float pv_st1[64];           // [sum32 | sumsq32]
static __device__ float pv_st2[128];          // [sum64 | sumsq64]
static __device__ float pv_ab1[64];           // [a32 | c32]
static __device__ float pv_ab2[128];          // [a64 | c64]

// ---------------- packed f32x2 (FFMA2: 2x fp32 rate vs 3-reg FFMA) ----------
__device__ __forceinline__ u64 pk2(float a, float b) {
    u64 r; asm("mov.b64 %0,{%1,%2};" : "=l"(r) : "f"(a), "f"(b)); return r;
}
__device__ __forceinline__ void upk2(u64 v, float& a, float& b) {
    asm("mov.b64 {%0,%1},%2;" : "=f"(a), "=f"(b) : "l"(v));
}
__device__ __forceinline__ u64 fma2(u64 a, u64 b, u64 c) {
    u64 d; asm("fma.rn.f32x2 %0,%1,%2,%3;" : "=l"(d) : "l"(a), "l"(b), "l"(c)); return d;
}
__device__ __forceinline__ u64 add2(u64 a, u64 b) {
    u64 d; asm("add.rn.f32x2 %0,%1,%2;" : "=l"(d) : "l"(a), "l"(b)); return d;
}

// ---------------- ordered-uint float encoding for atomicMax -----------------
// monotone bijection; every finite float encodes to a value > 0, so enc==0
// (the memset init) marks "empty". NaN never occurs for these inputs.
__device__ __forceinline__ u32 encf(float f) {
    u32 u = __float_as_uint(f);
    return ((int)u < 0) ? ~u : (u | 0x80000000u);
}
__device__ __forceinline__ float decf(u32 e) {
    return __uint_as_float(((int)e < 0) ? (e & 0x7fffffffu) : ~e);
}

// ---------------- per-point 11-feature build --------------------------------
__device__ __forceinline__ void build_feat(
    const float* __restrict__ xyz, const float* __restrict__ pf,
    int i, int v, float f[11])
{
    float px = xyz[3 * i + 0], py = xyz[3 * i + 1], pz = xyz[3 * i + 2];
    float mx = pv_vmean[3 * v + 0], my = pv_vmean[3 * v + 1], mz = pv_vmean[3 * v + 2];
    float cx = floorf((px - PMX) / VS);
    float cy = floorf((py - PMY) / VS);
    float cz = floorf((pz - PMZ) / VS);
    f[0] = px; f[1] = py; f[2] = pz; f[3] = pf[i];
    f[4] = px - mx; f[5] = py - my; f[6] = pz - mz;
    f[7] = px - (cx * VS + (0.5f * VS + PMX));
    f[8] = py - (cy * VS + (0.5f * VS + PMY));
    f[9] = pz - (cz * VS + (0.5f * VS + PMZ));
    f[10] = sqrtf(px * px + py * py + pz * pz);
}

// y1 = feat @ w1  (32 channels as 16 packed f32x2)
__device__ __forceinline__ void mm1(const u64* __restrict__ s_w1,
                                    const float f[11], u64 y[16])
{
#pragma unroll
    for (int j = 0; j < 16; j++) y[j] = 0ull;
#pragma unroll
    for (int k = 0; k < 11; k++) {
        u64 xk = pk2(f[k], f[k]);
#pragma unroll
        for (int j = 0; j < 16; j++) y[j] = fma2(xk, s_w1[k * 16 + j], y[j]);
    }
}

// ---------------- K1: per-voxel count + xyz sum -----------------------------
__global__ void __launch_bounds__(256) k_count(
    const float* __restrict__ xyz, const int* __restrict__ uinv, int n)
{
    int stride = gridDim.x * 256;
    for (int i = blockIdx.x * 256 + threadIdx.x; i < n; i += stride) {
        int v = uinv[i];
        atomicAdd(&pv_cnt[v], 1.0f);
        atomicAdd(&pv_vmean[3 * v + 0], xyz[3 * i + 0]);
        atomicAdd(&pv_vmean[3 * v + 1], xyz[3 * i + 1]);
        atomicAdd(&pv_vmean[3 * v + 2], xyz[3 * i + 2]);
    }
}

__global__ void __launch_bounds__(256) k_vmean() {
    int v = blockIdx.x * 256 + threadIdx.x;
    if (v < NVOX) {
        float inv = 1.0f / fmaxf(pv_cnt[v], 1.0f);
        pv_vmean[3 * v + 0] *= inv;
        pv_vmean[3 * v + 1] *= inv;
        pv_vmean[3 * v + 2] *= inv;
    }
}

// ---------------- K2: layer 1 — BN stats + raw segmax, one pass -------------
__global__ void __launch_bounds__(256) k_layer1(
    const float* __restrict__ xyz, const float* __restrict__ pf,
    const int* __restrict__ uinv, const float* __restrict__ w1, int n)
{
    __shared__ u64 s_w1[176];
    __shared__ float s_st[64];
    int tid = threadIdx.x;
    if (tid < 176) s_w1[tid] = ((const u64*)w1)[tid];
    if (tid < 64) s_st[tid] = 0.0f;
    __syncthreads();

    u64 sum[16], sq[16];
#pragma unroll
    for (int j = 0; j < 16; j++) { sum[j] = 0ull; sq[j] = 0ull; }

    int stride = gridDim.x * 256;
    for (int i = blockIdx.x * 256 + tid; i < n; i += stride) {
        int v = uinv[i];
        float f[11]; build_feat(xyz, pf, i, v, f);
        u64 y[16]; mm1(s_w1, f, y);
#pragma unroll
        for (int j = 0; j < 16; j++) {
            sum[j] = add2(sum[j], y[j]);
            sq[j] = fma2(y[j], y[j], sq[j]);
        }
        // load-filter: cell is monotone non-decreasing, so a stale (low) read
        // only causes a redundant atomic, never a missed update.
        u32* base = pv_seg1 + (size_t)v * 32;
        const uint4* c4 = (const uint4*)base;
#pragma unroll
        for (int q = 0; q < 8; q++) {
            uint4 cur = c4[q];
            float a0, a1, a2, a3;
            upk2(y[2 * q], a0, a1); upk2(y[2 * q + 1], a2, a3);
            u32 e0 = encf(a0), e1 = encf(a1), e2 = encf(a2), e3 = encf(a3);
            if (e0 > cur.x) atomicMax(base + 4 * q + 0, e0);
            if (e1 > cur.y) atomicMax(base + 4 * q + 1, e1);
            if (e2 > cur.z) atomicMax(base + 4 * q + 2, e2);
            if (e3 > cur.w) atomicMax(base + 4 * q + 3, e3);
        }
    }

    // warp butterfly -> shared -> global
    int lane = tid & 31;
#pragma unroll
    for (int j = 0; j < 16; j++) {
        float sa, sb, qa, qb;
        upk2(sum[j], sa, sb); upk2(sq[j], qa, qb);
#pragma unroll
        for (int o = 16; o > 0; o >>= 1) {
            sa += __shfl_xor_sync(0xffffffffu, sa, o);
            sb += __shfl_xor_sync(0xffffffffu, sb, o);
            qa += __shfl_xor_sync(0xffffffffu, qa, o);
            qb += __shfl_xor_sync(0xffffffffu, qb, o);
        }
        if (lane == 0) {
            atomicAdd(&s_st[2 * j], sa);
            atomicAdd(&s_st[2 * j + 1], sb);
            atomicAdd(&s_st[32 + 2 * j], qa);
            atomicAdd(&s_st[32 + 2 * j + 1], qb);
        }
    }
    __syncthreads();
    if (tid < 64) atomicAdd(&pv_st1[tid], s_st[tid]);
}

// ---------------- K3a: BN affine params layer 1 ------------------------------
__global__ void k_fin1(const float* __restrict__ g, const float* __restrict__ b,
                       float invn)
{
    int c = threadIdx.x;  // 32 threads
    float mu = pv_st1[c] * invn;
    float m2 = pv_st1[32 + c] * invn;
    double var = (double)m2 - (double)mu * (double)mu;
    if (var < 0.0) var = 0.0;
    float a = (float)((double)g[c] / sqrt(var + (double)BN_EPS));
    pv_ab1[c] = a;
    pv_ab1[32 + c] = fmaf(-mu, a, b[c]);
}

// ---------------- K3b: finalize layer-1 voxel features ----------------------
__global__ void __launch_bounds__(256) k_xmax1() {
    int i = (blockIdx.x * 256 + threadIdx.x) * 4;
    uint4 e = *(const uint4*)(pv_seg1 + i);
    int ch = i & 31;
    float4 r;
    r.x = e.x ? fmaxf(fmaf(pv_ab1[ch + 0], decf(e.x), pv_ab1[32 + ch + 0]), 0.0f) : 0.0f;
    r.y = e.y ? fmaxf(fmaf(pv_ab1[ch + 1], decf(e.y), pv_ab1[32 + ch + 1]), 0.0f) : 0.0f;
    r.z = e.z ? fmaxf(fmaf(pv_ab1[ch + 2], decf(e.z), pv_ab1[32 + ch + 2]), 0.0f) : 0.0f;
    r.w = e.w ? fmaxf(fmaf(pv_ab1[ch + 3], decf(e.w), pv_ab1[32 + ch + 3]), 0.0f) : 0.0f;
    *(float4*)(pv_xmax + i) = r;
}

// ---------------- K4: layer 2 — recompute x, GEMM64x64, stats + segmax ------
__global__ void __launch_bounds__(256) k_layer2(
    const float* __restrict__ xyz, const float* __restrict__ pf,
    const int* __restrict__ uinv, const float* __restrict__ w1,
    const float* __restrict__ w2, int n)
{
    __shared__ u64 s_w2[2048];   // w2 as 32 channel-pairs x 64 k-rows (16 KB)
    __shared__ u64 s_w1[176];
    __shared__ float s_ab[64];
    __shared__ float s_st[128];
    int tid = threadIdx.x;
    for (int t = tid; t < 2048; t += 256) s_w2[t] = ((const u64*)w2)[t];
    if (tid < 176) s_w1[tid] = ((const u64*)w1)[tid];
    if (tid < 64) s_ab[tid] = pv_ab1[tid];
    if (tid < 128) s_st[tid] = 0.0f;
    __syncthreads();

    int lane = tid & 31;
    int stride = gridDim.x * 256;
    // warp-uniform trip count so the in-loop butterflies are full-warp
    for (int i0 = blockIdx.x * 256 + (tid & ~31); i0 < n; i0 += stride) {
        int i = i0 + lane;
        bool act = (i < n);
        int ic = act ? i : (n - 1);
        int v = uinv[ic];

        float f[11]; build_feat(xyz, pf, ic, v, f);
        u64 y[16]; mm1(s_w1, f, y);

        float x[64];
#pragma unroll
        for (int j = 0; j < 16; j++) {
            float ya, yb; upk2(y[j], ya, yb);
            x[2 * j]     = fmaxf(fmaf(s_ab[2 * j],     ya, s_ab[32 + 2 * j]),     0.0f);
            x[2 * j + 1] = fmaxf(fmaf(s_ab[2 * j + 1], yb, s_ab[32 + 2 * j + 1]), 0.0f);
        }
        const float4* xm = (const float4*)(pv_xmax + (size_t)v * 32);
#pragma unroll
        for (int q = 0; q < 8; q++) {
            float4 t = xm[q];
            x[32 + 4 * q + 0] = t.x; x[32 + 4 * q + 1] = t.y;
            x[32 + 4 * q + 2] = t.z; x[32 + 4 * q + 3] = t.w;
        }
        if (!act) {
#pragma unroll
            for (int k = 0; k < 64; k++) x[k] = 0.0f;
        }

#pragma unroll
        for (int h = 0; h < 2; h++) {      // 32 output channels per half
            u64 acc[16];
#pragma unroll
            for (int j = 0; j < 16; j++) acc[j] = 0ull;
#pragma unroll
            for (int k = 0; k < 64; k++) {
                u64 xk = pk2(x[k], x[k]);
                const u64* wr = &s_w2[k * 32 + h * 16];
#pragma unroll
                for (int j = 0; j < 16; j++) acc[j] = fma2(xk, wr[j], acc[j]);
            }
            // stats: warp butterfly (inactive lanes contribute exact zeros)
#pragma unroll
            for (int j = 0; j < 16; j++) {
                float sa, sb; upk2(acc[j], sa, sb);
                float qa = sa * sa, qb = sb * sb;
#pragma unroll
                for (int o = 16; o > 0; o >>= 1) {
                    sa += __shfl_xor_sync(0xffffffffu, sa, o);
                    sb += __shfl_xor_sync(0xffffffffu, sb, o);
                    qa += __shfl_xor_sync(0xffffffffu, qa, o);
                    qb += __shfl_xor_sync(0xffffffffu, qb, o);
                }
                if (lane == 0) {
                    int c = h * 32 + 2 * j;
                    atomicAdd(&s_st[c], sa);
                    atomicAdd(&s_st[c + 1], sb);
                    atomicAdd(&s_st[64 + c], qa);
                    atomicAdd(&s_st[64 + c + 1], qb);
                }
            }
            // filtered segmax
            if (act) {
                u32* base = pv_seg2 + (size_t)v * 64 + h * 32;
                const uint4* c4 = (const uint4*)base;
#pragma unroll
                for (int q = 0; q < 8; q++) {
                    uint4 cur = c4[q];
                    float a0, a1, a2, a3;
                    upk2(acc[2 * q], a0, a1); upk2(acc[2 * q + 1], a2, a3);
                    u32 e0 = encf(a0), e1 = encf(a1), e2 = encf(a2), e3 = encf(a3);
                    if (e0 > cur.x) atomicMax(base + 4 * q + 0, e0);
                    if (e1 > cur.y) atomicMax(base + 4 * q + 1, e1);
                    if (e2 > cur.z) atomicMax(base + 4 * q + 2, e2);
                    if (e3 > cur.w) atomicMax(base + 4 * q + 3, e3);
                }
            }
        }
    }
    __syncthreads();
    if (tid < 128) atomicAdd(&pv_st2[tid], s_st[tid]);
}

// ---------------- K5a: BN affine params layer 2 ------------------------------
__global__ void k_fin2(const float* __restrict__ g, const float* __restrict__ b,
                       float invn)
{
    int c = threadIdx.x;  // 64 threads
    float mu = pv_st2[c] * invn;
    float m2 = pv_st2[64 + c] * invn;
    double var = (double)m2 - (double)mu * (double)mu;
    if (var < 0.0) var = 0.0;
    float a = (float)((double)g[c] / sqrt(var + (double)BN_EPS));
    pv_ab2[c] = a;
    pv_ab2[64 + c] = fmaf(-mu, a, b[c]);
}

// ---------------- K5b: finalize output ---------------------------------------
__global__ void __launch_bounds__(256) k_out(float* __restrict__ out) {
    int i = (blockIdx.x * 256 + threadIdx.x) * 4;
    uint4 e = *(const uint4*)(pv_seg2 + i);
    int ch = i & 63;
    float4 r;
    r.x = e.x ? fmaxf(fmaf(pv_ab2[ch + 0], decf(e.x), pv_ab2[64 + ch + 0]), 0.0f) : 0.0f;
    r.y = e.y ? fmaxf(fmaf(pv_ab2[ch + 1], decf(e.y), pv_ab2[64 + ch + 1]), 0.0f) : 0.0f;
    r.z = e.z ? fmaxf(fmaf(pv_ab2[ch + 2], decf(e.z), pv_ab2[64 + ch + 2]), 0.0f) : 0.0f;
    r.w = e.w ? fmaxf(fmaf(pv_ab2[ch + 3], decf(e.w), pv_ab2[64 + ch + 3]), 0.0f) : 0.0f;
    *(float4*)(out + i) = r;
}

// ---------------- launch -----------------------------------------------------
extern "C" void kernel_launch(void* const* d_in, const int* in_sizes, int n_in,
                              void* d_out, int out_size)
{
    const float* xyz = (const float*)d_in[0];
    const float* pf  = (const float*)d_in[1];
    const float* w1  = (const float*)d_in[2];
    const float* g1  = (const float*)d_in[3];
    const float* b1  = (const float*)d_in[4];
    const float* w2  = (const float*)d_in[5];
    const float* g2  = (const float*)d_in[6];
    const float* b2  = (const float*)d_in[7];
    const int*  uinv = (const int*)d_in[8];
    float* out = (float*)d_out;
    int n = in_sizes[1];
    float invn = 1.0f / (float)n;

    void* p;
    cudaGetSymbolAddress(&p, pv_cnt);   cudaMemsetAsync(p, 0, NVOX * sizeof(float));
    cudaGetSymbolAddress(&p, pv_vmean); cudaMemsetAsync(p, 0, NVOX * 3 * sizeof(float));
    cudaGetSymbolAddress(&p, pv_seg1);  cudaMemsetAsync(p, 0, NVOX * 32 * sizeof(u32));
    cudaGetSymbolAddress(&p, pv_seg2);  cudaMemsetAsync(p, 0, NVOX * 64 * sizeof(u32));
    cudaGetSymbolAddress(&p, pv_st1);   cudaMemsetAsync(p, 0, 64 * sizeof(float));
    cudaGetSymbolAddress(&p, pv_st2);   cudaMemsetAsync(p, 0, 128 * sizeof(float));

    int nb = (n + 255) / 256;
    k_count<<<nb, 256>>>(xyz, uinv, n);
    k_vmean<<<NVOX / 256, 256>>>();
    k_layer1<<<1184, 256>>>(xyz, pf, uinv, w1, n);
    k_fin1<<<1, 32>>>(g1, b1, invn);
    k_xmax1<<<NVOX * 32 / 1024, 256>>>();
    k_layer2<<<1184, 256>>>(xyz, pf, uinv, w1, w2, n);
    k_fin2<<<1, 64>>>(g2, b2, invn);
    k_out<<<NVOX * 64 / 1024, 256>>>(out);
}